// round 2
// baseline (speedup 1.0000x reference)
#include <cuda_runtime.h>
#include <cuda_bf16.h>

#define NN 8192            // support size
#define THREADS 1024       // threads per block
#define EPT 8              // elements per thread (THREADS*EPT == NN)

__device__ float g_cb[NN]; // inclusive cumsum of bary

// ---------------------------------------------------------------------------
// Block-wide exclusive scan of per-thread values (float). blockDim.x == 1024.
// Returns exclusive prefix for this thread.
// ---------------------------------------------------------------------------
__device__ __forceinline__ float block_exclusive_scan(float v, float* ws)
{
    const int lane = threadIdx.x & 31;
    const int wid  = threadIdx.x >> 5;

    float x = v;
    #pragma unroll
    for (int o = 1; o < 32; o <<= 1) {
        float y = __shfl_up_sync(0xFFFFFFFFu, x, o);
        if (lane >= o) x += y;
    }
    if (lane == 31) ws[wid] = x;
    __syncthreads();

    if (wid == 0) {
        float w = (lane < (THREADS >> 5)) ? ws[lane] : 0.0f;
        #pragma unroll
        for (int o = 1; o < 32; o <<= 1) {
            float y = __shfl_up_sync(0xFFFFFFFFu, w, o);
            if (lane >= o) w += y;
        }
        ws[lane] = w;                    // inclusive scan of warp sums
    }
    __syncthreads();

    float warp_off = (wid > 0) ? ws[wid - 1] : 0.0f;
    return warp_off + (x - v);           // exclusive prefix
}

// ---------------------------------------------------------------------------
// Kernel A: cb = cumsum(bary); out[1..N] = bary; out[0] = 0.  One block.
// ---------------------------------------------------------------------------
__global__ void init_kernel(const float* __restrict__ bary,
                            float* __restrict__ out, int out_size)
{
    __shared__ float ws[32];
    const int t = threadIdx.x;

    const float4* bp = reinterpret_cast<const float4*>(bary);
    float4 a = bp[t * 2 + 0];
    float4 b = bp[t * 2 + 1];

    float l0 = a.x;
    float l1 = l0 + a.y;
    float l2 = l1 + a.z;
    float l3 = l2 + a.w;
    float l4 = l3 + b.x;
    float l5 = l4 + b.y;
    float l6 = l5 + b.z;
    float l7 = l6 + b.w;

    float off = block_exclusive_scan(l7, ws);

    float4* cbp = reinterpret_cast<float4*>(g_cb);
    float4 c0, c1;
    c0.x = off + l0;  c0.y = off + l1;  c0.z = off + l2;  c0.w = off + l3;
    c1.x = off + l4;  c1.y = off + l5;  c1.z = off + l6;  c1.w = off + l7;
    cbp[t * 2 + 0] = c0;
    cbp[t * 2 + 1] = c1;

    // Copy bary into the output tail (tuple layout: [loss, bary...]).
    // out+1 is only 4B-aligned -> scalar stores.
    if (out_size >= NN + 1) {
        #pragma unroll
        for (int i = 0; i < EPT; ++i) {
            int idx = t * EPT + i;
            out[1 + idx] = (i < 4) ? (&a.x)[i] : (&b.x)[i - 4];
        }
    }
    if (t == 0) out[0] = 0.0f;
}

// ---------------------------------------------------------------------------
// Kernel B: per-row cumsum, L1 distance to g_cb over first N-1 entries,
// atomicAdd row result into out[0]. gridDim.x == D, blockDim.x == 1024.
// ---------------------------------------------------------------------------
__global__ void __launch_bounds__(THREADS)
row_w1_kernel(const float* __restrict__ x, float* __restrict__ out)
{
    __shared__ float ws[32];
    __shared__ float red[32];

    const int t = threadIdx.x;
    const float4* xp = reinterpret_cast<const float4*>(
        x + (size_t)blockIdx.x * NN);

    float4 a = xp[t * 2 + 0];
    float4 b = xp[t * 2 + 1];

    float l0 = a.x;
    float l1 = l0 + a.y;
    float l2 = l1 + a.z;
    float l3 = l2 + a.w;
    float l4 = l3 + b.x;
    float l5 = l4 + b.y;
    float l6 = l5 + b.z;
    float l7 = l6 + b.w;

    float off = block_exclusive_scan(l7, ws);

    const float4* cbp = reinterpret_cast<const float4*>(g_cb);
    float4 c0 = __ldg(cbp + t * 2 + 0);
    float4 c1 = __ldg(cbp + t * 2 + 1);

    float acc = fabsf(off + l0 - c0.x)
              + fabsf(off + l1 - c0.y)
              + fabsf(off + l2 - c0.z)
              + fabsf(off + l3 - c0.w)
              + fabsf(off + l4 - c1.x)
              + fabsf(off + l5 - c1.y)
              + fabsf(off + l6 - c1.z);
    if (t != THREADS - 1)                       // exclude global index N-1
        acc += fabsf(off + l7 - c1.w);

    // block reduction of acc
    const int lane = t & 31;
    const int wid  = t >> 5;
    #pragma unroll
    for (int o = 16; o > 0; o >>= 1)
        acc += __shfl_down_sync(0xFFFFFFFFu, acc, o);
    if (lane == 0) red[wid] = acc;
    __syncthreads();
    if (wid == 0) {
        float v = (lane < (THREADS >> 5)) ? red[lane] : 0.0f;
        #pragma unroll
        for (int o = 16; o > 0; o >>= 1)
            v += __shfl_down_sync(0xFFFFFFFFu, v, o);
        if (lane == 0) atomicAdd(out, v);
    }
}

// ---------------------------------------------------------------------------
extern "C" void kernel_launch(void* const* d_in, const int* in_sizes, int n_in,
                              void* d_out, int out_size)
{
    const float* x    = (const float*)d_in[0];   // [D, N] f32
    const float* bary = (const float*)d_in[1];   // [N] f32
    float* out = (float*)d_out;

    const int N = in_sizes[1];
    const int D = in_sizes[0] / N;
    (void)N; (void)n_in;

    init_kernel<<<1, THREADS>>>(bary, out, out_size);
    row_w1_kernel<<<D, THREADS>>>(x, out);
}

// round 3
// speedup vs baseline: 1.1003x; 1.1003x over previous
#include <cuda_runtime.h>
#include <cuda_bf16.h>

#define NN      8192
#define THREADS 512
#define EPT     16              // elements per thread (THREADS*EPT == NN)
#define VEC     (EPT/4)         // float4 loads per thread per row
#define RPB     8               // rows per block
#define NWARPS  (THREADS/32)

#define ITHREADS 1024           // init kernel config
#define IEPT     8

__device__ float g_cb[NN];      // inclusive cumsum of bary

// ---------------------------------------------------------------------------
// Kernel A: cb = cumsum(bary); out[1..N] = bary; out[0] = 0.  One block.
// ---------------------------------------------------------------------------
__global__ void __launch_bounds__(ITHREADS)
init_kernel(const float* __restrict__ bary, float* __restrict__ out,
            int out_size)
{
    __shared__ float ws[32];
    const int t = threadIdx.x;
    const int lane = t & 31, wid = t >> 5;

    const float4* bp = reinterpret_cast<const float4*>(bary);
    float4 a = bp[t * 2 + 0];
    float4 b = bp[t * 2 + 1];

    float l0 = a.x;
    float l1 = l0 + a.y;
    float l2 = l1 + a.z;
    float l3 = l2 + a.w;
    float l4 = l3 + b.x;
    float l5 = l4 + b.y;
    float l6 = l5 + b.z;
    float l7 = l6 + b.w;

    // block exclusive scan of per-thread totals (l7)
    float s = l7;
    #pragma unroll
    for (int o = 1; o < 32; o <<= 1) {
        float y = __shfl_up_sync(0xFFFFFFFFu, s, o);
        if (lane >= o) s += y;
    }
    if (lane == 31) ws[wid] = s;
    __syncthreads();
    float w = (lane < 32) ? ws[lane] : 0.0f;
    #pragma unroll
    for (int o = 1; o < 32; o <<= 1) {
        float y = __shfl_up_sync(0xFFFFFFFFu, w, o);
        if (lane >= o) w += y;
    }
    float warp_off = (wid > 0) ? __shfl_sync(0xFFFFFFFFu, w, wid - 1) : 0.0f;
    float off = warp_off + (s - l7);

    float4* cbp = reinterpret_cast<float4*>(g_cb);
    float4 c0, c1;
    c0.x = off + l0;  c0.y = off + l1;  c0.z = off + l2;  c0.w = off + l3;
    c1.x = off + l4;  c1.y = off + l5;  c1.z = off + l6;  c1.w = off + l7;
    cbp[t * 2 + 0] = c0;
    cbp[t * 2 + 1] = c1;

    // Copy bary into the output tail (tuple layout: [loss, bary...]).
    if (out_size >= NN + 1) {
        #pragma unroll
        for (int i = 0; i < IEPT; ++i) {
            int idx = t * IEPT + i;
            out[1 + idx] = (i < 4) ? (&a.x)[i] : (&b.x)[i - 4];
        }
    }
    if (t == 0) out[0] = 0.0f;
}

// ---------------------------------------------------------------------------
// Kernel B: RPB rows per block. cb held in registers (loaded once per block).
// Per row: 4x LDG.128, register scan of 16, ONE-barrier block scan
// (redundant warp-sum scan in every warp, ws double-buffered), accumulate
// |ca - cb| into a per-thread total. One reduction + one atomicAdd per block.
// ---------------------------------------------------------------------------
__global__ void __launch_bounds__(THREADS, 2)
row_w1_kernel(const float* __restrict__ x, float* __restrict__ out, int D)
{
    __shared__ float ws[2][NWARPS];
    __shared__ float red[NWARPS];

    const int t    = threadIdx.x;
    const int lane = t & 31;
    const int wid  = t >> 5;

    // cb for this thread's 16 columns -> registers, reused for all RPB rows
    float4 cb0, cb1, cb2, cb3;
    {
        const float4* cbp = reinterpret_cast<const float4*>(g_cb);
        cb0 = cbp[t * VEC + 0];
        cb1 = cbp[t * VEC + 1];
        cb2 = cbp[t * VEC + 2];
        cb3 = cbp[t * VEC + 3];
    }

    float total = 0.0f;
    const size_t row0 = (size_t)blockIdx.x * RPB;

    #pragma unroll 1
    for (int r = 0; r < RPB; ++r) {
        if (row0 + r >= (size_t)D) break;
        const float4* xp =
            reinterpret_cast<const float4*>(x + (row0 + r) * NN) + t * VEC;

        // front-batched loads (MLP = 4)
        float4 v0 = xp[0];
        float4 v1 = xp[1];
        float4 v2 = xp[2];
        float4 v3 = xp[3];

        // per-thread inclusive scan of 16 elements (in place)
        float l00 = v0.x;
        float l01 = l00 + v0.y;
        float l02 = l01 + v0.z;
        float l03 = l02 + v0.w;
        float l04 = l03 + v1.x;
        float l05 = l04 + v1.y;
        float l06 = l05 + v1.z;
        float l07 = l06 + v1.w;
        float l08 = l07 + v2.x;
        float l09 = l08 + v2.y;
        float l10 = l09 + v2.z;
        float l11 = l10 + v2.w;
        float l12 = l11 + v3.x;
        float l13 = l12 + v3.y;
        float l14 = l13 + v3.z;
        float l15 = l14 + v3.w;

        // warp inclusive scan of thread totals
        float s = l15;
        #pragma unroll
        for (int o = 1; o < 32; o <<= 1) {
            float y = __shfl_up_sync(0xFFFFFFFFu, s, o);
            if (lane >= o) s += y;
        }
        if (lane == 31) ws[r & 1][wid] = s;
        __syncthreads();

        // every warp redundantly scans the NWARPS warp sums (no 2nd barrier)
        float w = (lane < NWARPS) ? ws[r & 1][lane] : 0.0f;
        #pragma unroll
        for (int o = 1; o < NWARPS; o <<= 1) {
            float y = __shfl_up_sync(0xFFFFFFFFu, w, o);
            if (lane >= o) w += y;
        }
        float warp_off = (wid > 0) ? __shfl_sync(0xFFFFFFFFu, w, wid - 1) : 0.0f;
        float off = warp_off + (s - l15);   // exclusive prefix for this thread

        float acc;
        acc  = fabsf(off + l00 - cb0.x);
        acc += fabsf(off + l01 - cb0.y);
        acc += fabsf(off + l02 - cb0.z);
        acc += fabsf(off + l03 - cb0.w);
        acc += fabsf(off + l04 - cb1.x);
        acc += fabsf(off + l05 - cb1.y);
        acc += fabsf(off + l06 - cb1.z);
        acc += fabsf(off + l07 - cb1.w);
        acc += fabsf(off + l08 - cb2.x);
        acc += fabsf(off + l09 - cb2.y);
        acc += fabsf(off + l10 - cb2.z);
        acc += fabsf(off + l11 - cb2.w);
        acc += fabsf(off + l12 - cb3.x);
        acc += fabsf(off + l13 - cb3.y);
        acc += fabsf(off + l14 - cb3.z);
        acc += fabsf(off + l15 - cb3.w);
        if (t == THREADS - 1)               // exclude global index N-1
            acc -= fabsf(off + l15 - cb3.w);

        total += acc;
    }

    // block reduction of per-thread totals, one atomic per block
    #pragma unroll
    for (int o = 16; o > 0; o >>= 1)
        total += __shfl_down_sync(0xFFFFFFFFu, total, o);
    if (lane == 0) red[wid] = total;
    __syncthreads();
    if (wid == 0) {
        float v = (lane < NWARPS) ? red[lane] : 0.0f;
        #pragma unroll
        for (int o = NWARPS / 2; o > 0; o >>= 1)
            v += __shfl_down_sync(0xFFFFFFFFu, v, o);
        if (lane == 0) atomicAdd(out, v);
    }
}

// ---------------------------------------------------------------------------
extern "C" void kernel_launch(void* const* d_in, const int* in_sizes, int n_in,
                              void* d_out, int out_size)
{
    const float* x    = (const float*)d_in[0];   // [D, N] f32
    const float* bary = (const float*)d_in[1];   // [N] f32
    float* out = (float*)d_out;

    const int N = in_sizes[1];
    const int D = in_sizes[0] / N;
    (void)n_in;

    init_kernel<<<1, ITHREADS>>>(bary, out, out_size);

    const int grid = (D + RPB - 1) / RPB;
    row_w1_kernel<<<grid, THREADS>>>(x, out, D);
}

// round 4
// speedup vs baseline: 1.2456x; 1.1320x over previous
#include <cuda_runtime.h>
#include <cuda_bf16.h>

#define NN      8192
#define THREADS 512
#define EPT     16              // elements per thread (THREADS*EPT == NN)
#define VEC     (EPT/4)         // float4 loads per thread per row
#define NWARPS  (THREADS/32)
#define GBLOCKS 296             // 2 * 148 SMs -> single resident wave

#define ITHREADS 1024
#define IEPT     8

__device__ float g_cb[NN];      // inclusive cumsum of bary

// ---------------------------------------------------------------------------
// Kernel A: cb = cumsum(bary); out[1..N] = bary; out[0] = 0.  One block.
// ---------------------------------------------------------------------------
__global__ void __launch_bounds__(ITHREADS)
init_kernel(const float* __restrict__ bary, float* __restrict__ out,
            int out_size)
{
    __shared__ float ws[32];
    const int t = threadIdx.x;
    const int lane = t & 31, wid = t >> 5;

    const float4* bp = reinterpret_cast<const float4*>(bary);
    float4 a = bp[t * 2 + 0];
    float4 b = bp[t * 2 + 1];

    float l0 = a.x;
    float l1 = l0 + a.y;
    float l2 = l1 + a.z;
    float l3 = l2 + a.w;
    float l4 = l3 + b.x;
    float l5 = l4 + b.y;
    float l6 = l5 + b.z;
    float l7 = l6 + b.w;

    float s = l7;
    #pragma unroll
    for (int o = 1; o < 32; o <<= 1) {
        float y = __shfl_up_sync(0xFFFFFFFFu, s, o);
        if (lane >= o) s += y;
    }
    if (lane == 31) ws[wid] = s;
    __syncthreads();
    float w = (lane < 32) ? ws[lane] : 0.0f;
    #pragma unroll
    for (int o = 1; o < 32; o <<= 1) {
        float y = __shfl_up_sync(0xFFFFFFFFu, w, o);
        if (lane >= o) w += y;
    }
    float warp_off = (wid > 0) ? __shfl_sync(0xFFFFFFFFu, w, wid - 1) : 0.0f;
    float off = warp_off + (s - l7);

    float4* cbp = reinterpret_cast<float4*>(g_cb);
    float4 c0, c1;
    c0.x = off + l0;  c0.y = off + l1;  c0.z = off + l2;  c0.w = off + l3;
    c1.x = off + l4;  c1.y = off + l5;  c1.z = off + l6;  c1.w = off + l7;
    cbp[t * 2 + 0] = c0;
    cbp[t * 2 + 1] = c1;

    if (out_size >= NN + 1) {
        #pragma unroll
        for (int i = 0; i < IEPT; ++i) {
            int idx = t * IEPT + i;
            out[1 + idx] = (i < 4) ? (&a.x)[i] : (&b.x)[i - 4];
        }
    }
    if (t == 0) out[0] = 0.0f;
}

// ---------------------------------------------------------------------------
// Kernel B: persistent grid-stride over rows; cb in registers; software
// pipeline: issue next row's 4x LDG.128 BEFORE the current row's scan/
// shuffle/barrier so HBM loads stay in flight through the latency phase.
// One barrier per row; one atomicAdd per block.
// ---------------------------------------------------------------------------
__global__ void __launch_bounds__(THREADS, 2)
row_w1_kernel(const float* __restrict__ x, float* __restrict__ out, int D)
{
    __shared__ float ws[2][NWARPS];
    __shared__ float red[NWARPS];

    const int t    = threadIdx.x;
    const int lane = t & 31;
    const int wid  = t >> 5;
    const int G    = gridDim.x;

    // cb for this thread's 16 columns -> registers, reused for all rows
    float4 cb0, cb1, cb2, cb3;
    {
        const float4* cbp = reinterpret_cast<const float4*>(g_cb) + t * VEC;
        cb0 = cbp[0];
        cb1 = cbp[1];
        cb2 = cbp[2];
        cb3 = cbp[3];
    }

    const float4* base = reinterpret_cast<const float4*>(x);
    float total = 0.0f;

    int  row   = blockIdx.x;
    bool valid = (row < D);

    float4 v0, v1, v2, v3;
    if (valid) {
        const float4* p = base + (size_t)row * (NN / 4) + t * VEC;
        v0 = p[0]; v1 = p[1]; v2 = p[2]; v3 = p[3];
    }

    int it = 0;
    while (valid) {
        // ---- prefetch next row (uniform across block) ----
        const int  next   = row + G;
        const bool nvalid = (next < D);
        float4 w0, w1, w2, w3;
        if (nvalid) {
            const float4* p = base + (size_t)next * (NN / 4) + t * VEC;
            w0 = p[0]; w1 = p[1]; w2 = p[2]; w3 = p[3];
        }

        // ---- per-thread inclusive scan of 16 elements ----
        float l00 = v0.x;
        float l01 = l00 + v0.y;
        float l02 = l01 + v0.z;
        float l03 = l02 + v0.w;
        float l04 = l03 + v1.x;
        float l05 = l04 + v1.y;
        float l06 = l05 + v1.z;
        float l07 = l06 + v1.w;
        float l08 = l07 + v2.x;
        float l09 = l08 + v2.y;
        float l10 = l09 + v2.z;
        float l11 = l10 + v2.w;
        float l12 = l11 + v3.x;
        float l13 = l12 + v3.y;
        float l14 = l13 + v3.z;
        float l15 = l14 + v3.w;

        // ---- warp inclusive scan of thread totals ----
        float s = l15;
        #pragma unroll
        for (int o = 1; o < 32; o <<= 1) {
            float y = __shfl_up_sync(0xFFFFFFFFu, s, o);
            if (lane >= o) s += y;
        }
        if (lane == 31) ws[it & 1][wid] = s;
        __syncthreads();

        // ---- every warp redundantly scans the warp sums (no 2nd barrier) ----
        float w = (lane < NWARPS) ? ws[it & 1][lane] : 0.0f;
        #pragma unroll
        for (int o = 1; o < NWARPS; o <<= 1) {
            float y = __shfl_up_sync(0xFFFFFFFFu, w, o);
            if (lane >= o) w += y;
        }
        float warp_off = (wid > 0) ? __shfl_sync(0xFFFFFFFFu, w, wid - 1) : 0.0f;
        float off = warp_off + (s - l15);   // exclusive prefix for this thread

        // ---- |ca - cb| accumulation ----
        float acc;
        acc  = fabsf(off + l00 - cb0.x);
        acc += fabsf(off + l01 - cb0.y);
        acc += fabsf(off + l02 - cb0.z);
        acc += fabsf(off + l03 - cb0.w);
        acc += fabsf(off + l04 - cb1.x);
        acc += fabsf(off + l05 - cb1.y);
        acc += fabsf(off + l06 - cb1.z);
        acc += fabsf(off + l07 - cb1.w);
        acc += fabsf(off + l08 - cb2.x);
        acc += fabsf(off + l09 - cb2.y);
        acc += fabsf(off + l10 - cb2.z);
        acc += fabsf(off + l11 - cb2.w);
        acc += fabsf(off + l12 - cb3.x);
        acc += fabsf(off + l13 - cb3.y);
        acc += fabsf(off + l14 - cb3.z);
        if (t != THREADS - 1)               // exclude global index N-1
            acc += fabsf(off + l15 - cb3.w);

        total += acc;

        // ---- rotate pipeline ----
        v0 = w0; v1 = w1; v2 = w2; v3 = w3;
        row = next; valid = nvalid; ++it;
    }

    // block reduction of per-thread totals, one atomic per block
    #pragma unroll
    for (int o = 16; o > 0; o >>= 1)
        total += __shfl_down_sync(0xFFFFFFFFu, total, o);
    if (lane == 0) red[wid] = total;
    __syncthreads();
    if (wid == 0) {
        float v = (lane < NWARPS) ? red[lane] : 0.0f;
        #pragma unroll
        for (int o = NWARPS / 2; o > 0; o >>= 1)
            v += __shfl_down_sync(0xFFFFFFFFu, v, o);
        if (lane == 0) atomicAdd(out, v);
    }
}

// ---------------------------------------------------------------------------
extern "C" void kernel_launch(void* const* d_in, const int* in_sizes, int n_in,
                              void* d_out, int out_size)
{
    const float* x    = (const float*)d_in[0];   // [D, N] f32
    const float* bary = (const float*)d_in[1];   // [N] f32
    float* out = (float*)d_out;

    const int N = in_sizes[1];
    const int D = in_sizes[0] / N;
    (void)n_in;

    init_kernel<<<1, ITHREADS>>>(bary, out, out_size);

    const int grid = (D < GBLOCKS) ? D : GBLOCKS;
    row_w1_kernel<<<grid, THREADS>>>(x, out, D);
}